// round 9
// baseline (speedup 1.0000x reference)
#include <cuda_runtime.h>
#include <cuda_bf16.h>
#include <cuda_fp8.h>
#include <cstdint>
#include <math.h>

// ---------------- problem constants ----------------
#define N_UTT   2000
#define NODES   6000
#define KPAD    6016     // 47*128, 94*64
#define ND      200
#define NDP     208
#define ND2     400
#define NLAYERS 8
#define ADJ_SCALE 16384.0f
#define ADJ_INV   (1.0f / 16384.0f)

// ---------------- device scratch ----------------
static __device__ unsigned char g_adjF8[(size_t)KPAD * KPAD];    // e4m3, adj*2^14, 36.2 MB
static __device__ unsigned char g_HT8[(size_t)NDP * KPAD];       // e4m3 h^T [feat][node]
static __device__ float g_X [(size_t)NODES * ND];
static __device__ float g_H0[(size_t)NODES * ND];
static __device__ float g_Hf[(size_t)NODES * ND];
static __device__ float g_P[3][(size_t)KPAD * NDP];              // split-K partials (scaled by 2^14)
static __device__ __align__(16) float g_zeroF[4];                // zero-initialized

// ---------------- PTX helpers ----------------
__device__ __forceinline__ void cp16(void* s, const void* g) {
    uint32_t sa = (uint32_t)__cvta_generic_to_shared(s);
    asm volatile("cp.async.cg.shared.global [%0], [%1], 16;\n" :: "r"(sa), "l"(g));
}
__device__ __forceinline__ void cp8(void* s, const void* g) {
    uint32_t sa = (uint32_t)__cvta_generic_to_shared(s);
    asm volatile("cp.async.ca.shared.global [%0], [%1], 8;\n" :: "r"(sa), "l"(g));
}
__device__ __forceinline__ void cp_commit() { asm volatile("cp.async.commit_group;\n" ::); }
__device__ __forceinline__ void cp_wait1()  { asm volatile("cp.async.wait_group 1;\n" ::: "memory"); }

__device__ __forceinline__ void ldsm_x4(uint32_t* r, const void* p) {
    uint32_t sa = (uint32_t)__cvta_generic_to_shared(p);
    asm volatile("ldmatrix.sync.aligned.m8n8.x4.shared.b16 {%0,%1,%2,%3}, [%4];\n"
                 : "=r"(r[0]), "=r"(r[1]), "=r"(r[2]), "=r"(r[3]) : "r"(sa));
}
__device__ __forceinline__ void ldsm_x2(uint32_t* r, const void* p) {
    uint32_t sa = (uint32_t)__cvta_generic_to_shared(p);
    asm volatile("ldmatrix.sync.aligned.m8n8.x2.shared.b16 {%0,%1}, [%2];\n"
                 : "=r"(r[0]), "=r"(r[1]) : "r"(sa));
}
__device__ __forceinline__ void mma_e4m3(float* c, const uint32_t* a, const uint32_t* b) {
    asm volatile("mma.sync.aligned.m16n8k32.row.col.f32.e4m3.e4m3.f32 "
                 "{%0,%1,%2,%3},{%4,%5,%6,%7},{%8,%9},{%0,%1,%2,%3};\n"
                 : "+f"(c[0]), "+f"(c[1]), "+f"(c[2]), "+f"(c[3])
                 : "r"(a[0]), "r"(a[1]), "r"(a[2]), "r"(a[3]), "r"(b[0]), "r"(b[1]));
}
__device__ __forceinline__ void mma_tf32(float* c, uint32_t a0, uint32_t a1, uint32_t a2,
                                         uint32_t a3, uint32_t b0, uint32_t b1) {
    asm volatile("mma.sync.aligned.m16n8k8.row.col.f32.tf32.tf32.f32 "
                 "{%0,%1,%2,%3},{%4,%5,%6,%7},{%8,%9},{%0,%1,%2,%3};\n"
                 : "+f"(c[0]), "+f"(c[1]), "+f"(c[2]), "+f"(c[3])
                 : "r"(a0), "r"(a1), "r"(a2), "r"(a3), "r"(b0), "r"(b1));
}
__device__ __forceinline__ uint32_t f2tf32(float x) {
    uint32_t r; asm("cvt.rna.tf32.f32 %0, %1;" : "=r"(r) : "f"(x)); return r;
}
__device__ __forceinline__ uint16_t f2e4m3x2(float x, float y) {
    return __nv_cvt_float2_to_fp8x2(make_float2(x, y), __NV_SATFINITE, __NV_E4M3);
}
__device__ __forceinline__ unsigned char f2e4m3(float x) {
    return __nv_cvt_float_to_fp8(x, __NV_SATFINITE, __NV_E4M3);
}

// ---------------- adj fp32 -> e4m3 (scaled by 2^14), padded [KPAD x KPAD] ----------------
__global__ void k_conv_adj(const float* __restrict__ adj) {
    size_t idx = (size_t)blockIdx.x * blockDim.x + threadIdx.x;
    if (idx >= (size_t)KPAD * (KPAD / 8)) return;
    int r  = (int)(idx / (KPAD / 8));
    int c0 = (int)(idx % (KPAD / 8)) * 8;
    uint16_t o[4];
    if (r < NODES && c0 + 8 <= NODES) {
        const float4 v0 = *reinterpret_cast<const float4*>(adj + (size_t)r * NODES + c0);
        const float4 v1 = *reinterpret_cast<const float4*>(adj + (size_t)r * NODES + c0 + 4);
        o[0] = f2e4m3x2(v0.x * ADJ_SCALE, v0.y * ADJ_SCALE);
        o[1] = f2e4m3x2(v0.z * ADJ_SCALE, v0.w * ADJ_SCALE);
        o[2] = f2e4m3x2(v1.x * ADJ_SCALE, v1.y * ADJ_SCALE);
        o[3] = f2e4m3x2(v1.z * ADJ_SCALE, v1.w * ADJ_SCALE);
    } else {
        #pragma unroll
        for (int j = 0; j < 4; j++) {
            int c = c0 + j * 2;
            float x0 = (r < NODES && c     < NODES) ? adj[(size_t)r * NODES + c] * ADJ_SCALE : 0.f;
            float x1 = (r < NODES && c + 1 < NODES) ? adj[(size_t)r * NODES + c + 1] * ADJ_SCALE : 0.f;
            o[j] = f2e4m3x2(x0, x1);
        }
    }
    uint2 pk = make_uint2((uint32_t)o[0] | ((uint32_t)o[1] << 16),
                          (uint32_t)o[2] | ((uint32_t)o[3] << 16));
    *reinterpret_cast<uint2*>(g_adjF8 + (size_t)r * KPAD + c0) = pk;
}

// zero h^T e4m3 buffer (pads stay zero; valid region rewritten by epilogues)
__global__ void k_zero_ht8() {
    size_t i = (size_t)blockIdx.x * blockDim.x + threadIdx.x;
    if (i < (size_t)NDP * KPAD / 16)
        reinterpret_cast<uint4*>(g_HT8)[i] = make_uint4(0, 0, 0, 0);
}

// ---------------- adj GEMM (fp8): P[ksp] = adjF8[:,ks] @ h  (B = h^T, n-major) ----------
// BM=128, BN=208, BK=64, 3 stages, grid (47,3). 256 threads.
// smem row stride 80 BYTES (multiple of 16 -> ldmatrix alignment; 72 was the R7 bug).
#define AJ_LDA 80
#define AJ_A_B (128 * AJ_LDA)             // 10240
#define AJ_B_B (208 * AJ_LDA)             // 16640
#define AJ_STG (AJ_A_B + AJ_B_B)          // 26880
#define AJ_SMEM_BYTES (3 * AJ_STG)        // 80640

__global__ __launch_bounds__(256, 1) void k_adj_fp8() {
    extern __shared__ unsigned char aj[];

    const int tid  = threadIdx.x;
    const int lane = tid & 31;
    const int warp = tid >> 5;
    const int wm   = warp >> 1;
    const int wn   = warp & 1;
    const int bm0  = blockIdx.x * 128;
    const int ksp  = blockIdx.y;
    const int kbase = ksp * 2048;
    const int ITERS = (ksp == 2) ? 30 : 32;

    float acc[2][13][4];
    #pragma unroll
    for (int a = 0; a < 2; a++)
        #pragma unroll
        for (int i = 0; i < 13; i++)
            #pragma unroll
            for (int j = 0; j < 4; j++) acc[a][i][j] = 0.f;

    auto fill = [&](int st, int it) {
        const int k0 = kbase + it * 64;
        unsigned char* sA = aj + st * AJ_STG;
        unsigned char* sB = sA + AJ_A_B;
        #pragma unroll
        for (int v = tid; v < 512; v += 256) {          // A: 128 rows x 64 B
            int r = v >> 2, c = (v & 3) * 16;
            cp16(sA + r * AJ_LDA + c, g_adjF8 + (size_t)(bm0 + r) * KPAD + k0 + c);
        }
        #pragma unroll
        for (int v = tid; v < 832; v += 256) {          // B: 208 n-rows x 64 B
            int r = v >> 2, c = (v & 3) * 16;
            cp16(sB + r * AJ_LDA + c, g_HT8 + (size_t)r * KPAD + k0 + c);
        }
        cp_commit();
    };

    fill(0, 0); fill(1, 1);

    #pragma unroll 1
    for (int it = 0; it < ITERS; ++it) {
        cp_wait1();
        __syncthreads();
        const int st = it % 3;
        const unsigned char* sA = aj + st * AJ_STG;
        const unsigned char* sB = sA + AJ_A_B;
        #pragma unroll
        for (int ks = 0; ks < 2; ks++) {
            // A fragments: matrix j from lane-group j = lane>>3
            // j&1 -> m-half (+8 rows), j>>1 -> k-half (+16 bytes)
            uint32_t af[2][4];
            #pragma unroll
            for (int mf = 0; mf < 2; mf++) {
                int row = wm * 32 + mf * 16 + ((lane >> 3) & 1) * 8 + (lane & 7);
                int kof = ks * 32 + ((lane >> 4) << 4);
                ldsm_x4(af[mf], sA + row * AJ_LDA + kof);
            }
            // B fragments: matrix j: j>>1 -> n-group (+8), j&1 -> k-half (+16)
            uint32_t bf[13][2];
            #pragma unroll
            for (int p = 0; p < 6; p++) {
                int row = wn * 104 + (2 * p + (lane >> 4)) * 8 + (lane & 7);
                int kof = ks * 32 + (((lane >> 3) & 1) << 4);
                uint32_t r[4];
                ldsm_x4(r, sB + row * AJ_LDA + kof);
                bf[2 * p][0] = r[0];     bf[2 * p][1] = r[1];
                bf[2 * p + 1][0] = r[2]; bf[2 * p + 1][1] = r[3];
            }
            {
                int row = wn * 104 + 96 + (lane & 7);
                int kof = ks * 32 + (((lane >> 3) & 1) << 4);
                uint32_t r[2];
                ldsm_x2(r, sB + row * AJ_LDA + kof);
                bf[12][0] = r[0]; bf[12][1] = r[1];
            }
            #pragma unroll
            for (int mf = 0; mf < 2; mf++)
                #pragma unroll
                for (int nf = 0; nf < 13; nf++)
                    mma_e4m3(acc[mf][nf], af[mf], bf[nf]);
        }
        if (it + 2 < ITERS) fill((it + 2) % 3, it + 2);
        else                cp_commit();
    }

    // partial epilogue -> g_P[ksp] (values carry the 2^14 scale)
    float* P = g_P[ksp];
    #pragma unroll
    for (int mf = 0; mf < 2; mf++) {
        const int r0 = bm0 + wm * 32 + mf * 16 + (lane >> 2);
        #pragma unroll
        for (int nf = 0; nf < 13; nf++) {
            int c = wn * 104 + nf * 8 + ((lane & 3) << 1);
            *reinterpret_cast<float2*>(&P[(size_t)r0 * NDP + c]) =
                make_float2(acc[mf][nf][0], acc[mf][nf][1]);
            *reinterpret_cast<float2*>(&P[(size_t)(r0 + 8) * NDP + c]) =
                make_float2(acc[mf][nf][2], acc[mf][nf][3]);
        }
    }
}

// ---------------- tf32 GEMM body: C = A[M,K] @ W[K,200], fused epilogues ----------------
// BM=64, BN=208, BK=32, 3 stages. 256 threads.
// mode 0: X[row_off+m] = acc + bias
// mode 1: X[row_off+m] = acc + bias + spk_emb[argmax(qmask)]
// mode 2: h0 = relu(acc+bias) -> H0, HT8
// mode 3: A = [hi | h0] assembled on the fly (hi = (P0+P1+P2)*2^-14), K=400;
//         h = relu(theta*acc + (1-theta)*(0.9*hi + 0.1*h0)) -> Hf, HT8
#define G2_BM 64
#define G2_BK 32
#define G2_A_EL (G2_BM * 34)
#define G2_B_EL (G2_BK * 216)
#define G2_STG_EL (G2_A_EL + G2_B_EL)
#define G2_SMEM_BYTES (3 * G2_STG_EL * 4)    // 109056

__device__ __forceinline__ void g2_body(
    float* dyn, const float* __restrict__ A, int lda, int M, int K,
    const float* __restrict__ W, const float* __restrict__ bias,
    int mode, float theta, int row_off,
    const float* __restrict__ qmask, const float* __restrict__ spk_emb)
{
    const int tid  = threadIdx.x;
    const int lane = tid & 31;
    const int warp = tid >> 5;
    const int wm   = warp >> 1;
    const int wn   = warp & 1;
    const int bm0  = blockIdx.x * G2_BM;

    float acc[13][4];
    #pragma unroll
    for (int i = 0; i < 13; i++)
        #pragma unroll
        for (int j = 0; j < 4; j++) acc[i][j] = 0.f;

    auto fill = [&](int st, int it) {
        const int k0 = it * G2_BK;
        float* shA = dyn + st * G2_STG_EL;
        float* shB = shA + G2_A_EL;
        if (mode == 3) {
            // A = [hi | h0]: hi summed from split-K partials, scaled
            #pragma unroll
            for (int v = tid; v < 1024; v += 256) {   // 64 rows x 16 float2
                int m = v >> 4, kp = (v & 15) * 2;
                int gm = bm0 + m, gk = k0 + kp;
                float2 val = make_float2(0.f, 0.f);
                if (gm < M && gk < K) {
                    if (gk < ND) {
                        size_t o = (size_t)gm * NDP + gk;
                        float2 p0 = *reinterpret_cast<const float2*>(&g_P[0][o]);
                        float2 p1 = *reinterpret_cast<const float2*>(&g_P[1][o]);
                        float2 p2 = *reinterpret_cast<const float2*>(&g_P[2][o]);
                        val = make_float2((p0.x + p1.x + p2.x) * ADJ_INV,
                                          (p0.y + p1.y + p2.y) * ADJ_INV);
                    } else {
                        val = *reinterpret_cast<const float2*>(
                            &g_H0[(size_t)gm * ND + (gk - ND)]);
                    }
                }
                *reinterpret_cast<float2*>(shA + m * 34 + kp) = val;
            }
        } else {
            #pragma unroll
            for (int v = tid; v < 1024; v += 256) {
                int m = v >> 4, kp = (v & 15) * 2;
                int gm = bm0 + m, gk = k0 + kp;
                const float* src = (gm < M && gk < K) ? &A[(size_t)gm * lda + gk] : g_zeroF;
                cp8(shA + m * 34 + kp, src);
            }
        }
        for (int v = tid; v < 3328; v += 256) {      // B: 32 x 208
            int k = v / 104, np = (v % 104) * 2;
            int gk = k0 + k;
            const float* src = (gk < K && np < ND) ? &W[(size_t)gk * ND + np] : g_zeroF;
            cp8(shB + k * 216 + np, src);
        }
        cp_commit();
    };

    const int ITERS = (K + G2_BK - 1) / G2_BK;
    fill(0, 0);
    if (ITERS > 1) fill(1, 1); else cp_commit();

    const int mrow = wm * 16 + (lane >> 2);
    #pragma unroll 1
    for (int it = 0; it < ITERS; ++it) {
        cp_wait1();
        __syncthreads();
        const int st = it % 3;
        const float* shA = dyn + st * G2_STG_EL;
        const float* shB = shA + G2_A_EL;
        #pragma unroll
        for (int kb = 0; kb < G2_BK; kb += 8) {
            const int kk = kb + (lane & 3);
            uint32_t a0 = f2tf32(shA[mrow * 34 + kk]);
            uint32_t a1 = f2tf32(shA[(mrow + 8) * 34 + kk]);
            uint32_t a2 = f2tf32(shA[mrow * 34 + kk + 4]);
            uint32_t a3 = f2tf32(shA[(mrow + 8) * 34 + kk + 4]);
            #pragma unroll
            for (int nf = 0; nf < 13; nf++) {
                int nc = wn * 104 + nf * 8 + (lane >> 2);
                uint32_t b0 = f2tf32(shB[(kb + (lane & 3)) * 216 + nc]);
                uint32_t b1 = f2tf32(shB[(kb + 4 + (lane & 3)) * 216 + nc]);
                mma_tf32(acc[nf], a0, a1, a2, a3, b0, b1);
            }
        }
        if (it + 2 < ITERS) fill((it + 2) % 3, it + 2);
        else                cp_commit();
    }

    // fused epilogue
    const int mloc = wm * 16 + (lane >> 2);
    #pragma unroll
    for (int nf = 0; nf < 13; nf++) {
        int c = wn * 104 + nf * 8 + ((lane & 3) << 1);
        if (c >= ND) continue;
        #pragma unroll
        for (int half = 0; half < 2; half++) {
            int m = bm0 + mloc + half * 8;
            if (m >= M) continue;
            float v0 = acc[nf][half * 2], v1 = acc[nf][half * 2 + 1];
            if (mode <= 1) {
                float x0 = v0 + bias[c], x1 = v1 + bias[c + 1];
                if (mode == 1) {
                    int b = m / 100, t = m % 100;
                    float q0 = qmask[(t * 20 + b) * 2];
                    float q1 = qmask[(t * 20 + b) * 2 + 1];
                    int idx = (q1 > q0) ? 1 : 0;
                    x0 += spk_emb[idx * ND + c];
                    x1 += spk_emb[idx * ND + c + 1];
                }
                *reinterpret_cast<float2*>(&g_X[(size_t)(row_off + m) * ND + c]) =
                    make_float2(x0, x1);
            } else if (mode == 2) {
                float x0 = fmaxf(v0 + bias[c], 0.f);
                float x1 = fmaxf(v1 + bias[c + 1], 0.f);
                *reinterpret_cast<float2*>(&g_H0[(size_t)m * ND + c]) = make_float2(x0, x1);
                g_HT8[(size_t)c * KPAD + m]       = f2e4m3(x0);
                g_HT8[(size_t)(c + 1) * KPAD + m] = f2e4m3(x1);
            } else {
                size_t o = (size_t)m * NDP + c;
                float2 p0 = *reinterpret_cast<const float2*>(&g_P[0][o]);
                float2 p1 = *reinterpret_cast<const float2*>(&g_P[1][o]);
                float2 p2 = *reinterpret_cast<const float2*>(&g_P[2][o]);
                float hix = (p0.x + p1.x + p2.x) * ADJ_INV;
                float hiy = (p0.y + p1.y + p2.y) * ADJ_INV;
                float2 h0v = *reinterpret_cast<const float2*>(&g_H0[(size_t)m * ND + c]);
                float x0 = fmaxf(theta * v0 + (1.f - theta) * (0.9f * hix + 0.1f * h0v.x), 0.f);
                float x1 = fmaxf(theta * v1 + (1.f - theta) * (0.9f * hiy + 0.1f * h0v.y), 0.f);
                *reinterpret_cast<float2*>(&g_Hf[(size_t)m * ND + c]) = make_float2(x0, x1);
                g_HT8[(size_t)c * KPAD + m]       = f2e4m3(x0);
                g_HT8[(size_t)(c + 1) * KPAD + m] = f2e4m3(x1);
            }
        }
    }
}

// merged modality projections: grid (32, 3)
__global__ __launch_bounds__(256, 1) void k_proj(
    const float* __restrict__ a, const float* __restrict__ v, const float* __restrict__ l,
    const float* __restrict__ Wa, const float* __restrict__ ba,
    const float* __restrict__ Wv, const float* __restrict__ bv,
    const float* __restrict__ Wl, const float* __restrict__ bl,
    const float* __restrict__ qm, const float* __restrict__ spk)
{
    extern __shared__ float dyn[];
    if (blockIdx.y == 0)
        g2_body(dyn, a, 300,  N_UTT, 300,  Wa, ba, 0, 0.f, 0,    nullptr, nullptr);
    else if (blockIdx.y == 1)
        g2_body(dyn, v, 342,  N_UTT, 342,  Wv, bv, 0, 0.f, 2000, nullptr, nullptr);
    else
        g2_body(dyn, l, 1024, N_UTT, 1024, Wl, bl, 1, 0.f, 4000, qm, spk);
}

// generic tf32 GEMM. asel 1 -> A = g_X (mode 2); asel 2 -> mode 3 (A assembled in fill)
__global__ __launch_bounds__(256, 1) void k_gemm_tf32(
    int asel, int lda, int M, int K,
    const float* __restrict__ W, const float* __restrict__ bias,
    int mode, float theta)
{
    extern __shared__ float dyn[];
    const float* A = (asel == 1) ? g_X : g_H0;
    g2_body(dyn, A, lda, M, K, W, bias, mode, theta, 0, nullptr, nullptr);
}

// ---------------- output assembly: [2000, 1200] ----------------
__global__ void k_out(float* __restrict__ out) {
    int i = blockIdx.x * blockDim.x + threadIdx.x;
    if (i >= N_UTT * 1200) return;
    int r = i / 1200, c = i % 1200;
    int seg = c / ND, cc = c % ND;
    int chunk = seg >> 1;
    const float* src = (seg & 1) ? g_Hf : g_X;
    out[i] = src[(size_t)(chunk * N_UTT + r) * ND + cc];
}

// ---------------- launch ----------------
extern "C" void kernel_launch(void* const* d_in, const int* in_sizes, int n_in,
                              void* d_out, int out_size) {
    const float* a    = (const float*)d_in[0];
    const float* v    = (const float*)d_in[1];
    const float* l    = (const float*)d_in[2];
    const float* qm   = (const float*)d_in[3];
    const float* adj  = (const float*)d_in[4];
    const float* Wa   = (const float*)d_in[5];
    const float* ba   = (const float*)d_in[6];
    const float* Wv   = (const float*)d_in[7];
    const float* bv   = (const float*)d_in[8];
    const float* Wl   = (const float*)d_in[9];
    const float* bl   = (const float*)d_in[10];
    const float* spk  = (const float*)d_in[11];
    const float* W0   = (const float*)d_in[12];
    const float* b0   = (const float*)d_in[13];
    const float* convW= (const float*)d_in[14];
    float* out = (float*)d_out;

    cudaFuncSetAttribute(k_adj_fp8, cudaFuncAttributeMaxDynamicSharedMemorySize, AJ_SMEM_BYTES);
    cudaFuncSetAttribute(k_proj, cudaFuncAttributeMaxDynamicSharedMemorySize, G2_SMEM_BYTES);
    cudaFuncSetAttribute(k_gemm_tf32, cudaFuncAttributeMaxDynamicSharedMemorySize, G2_SMEM_BYTES);

    // 1. adj -> e4m3 (scaled); zero h^T buffer
    {
        size_t total = (size_t)KPAD * (KPAD / 8);
        k_conv_adj<<<(unsigned)((total + 255) / 256), 256>>>(adj);
    }
    {
        size_t chunks = (size_t)NDP * KPAD / 16;
        k_zero_ht8<<<(unsigned)((chunks + 255) / 256), 256>>>();
    }

    // 2. modality projections (one launch)
    {
        dim3 g((N_UTT + G2_BM - 1) / G2_BM, 3);
        k_proj<<<g, 256, G2_SMEM_BYTES>>>(a, v, l, Wa, ba, Wv, bv, Wl, bl, qm, spk);
    }

    // 3. h0 = relu(X @ W0 + b0) -> H0, HT8
    k_gemm_tf32<<<(NODES + G2_BM - 1) / G2_BM, 256, G2_SMEM_BYTES>>>(
        1, ND, NODES, ND, W0, b0, 2, 0.f);

    // 4. GCNII layers
    for (int k = 0; k < NLAYERS; ++k) {
        float theta = logf(0.5f / (float)(k + 1) + 1.0f);
        dim3 ga(KPAD / 128, 3);
        k_adj_fp8<<<ga, 256, AJ_SMEM_BYTES>>>();
        k_gemm_tf32<<<(NODES + G2_BM - 1) / G2_BM, 256, G2_SMEM_BYTES>>>(
            2, ND2, NODES, ND2, convW + (size_t)k * ND2 * ND, nullptr, 3, theta);
    }

    // 5. gather output
    k_out<<<(N_UTT * 1200 + 255) / 256, 256>>>(out);
}

// round 10
// speedup vs baseline: 1.0395x; 1.0395x over previous
#include <cuda_runtime.h>
#include <cuda_bf16.h>
#include <cstdint>
#include <math.h>

// ---------------- problem constants ----------------
#define N_UTT   2000
#define NODES   6000
#define KPAD    6016     // 47*128, 94*64
#define ND      200
#define NDP     208
#define ND2     400
#define NLAYERS 8

// W offsets inside g_Wtf (tf32-bit u32)
#define WA_OFF 0
#define WV_OFF 60000
#define WL_OFF 128400
#define W0_OFF 333200
#define WC_OFF 373200
#define W_TOTAL 1013200

// ---------------- device scratch ----------------
static __device__ __nv_bfloat16 g_adjBF[(size_t)KPAD * KPAD];    // 72.4 MB
static __device__ __nv_bfloat16 g_Hbf[(size_t)KPAD * NDP];       // h bf16 [node][feat], pads 0
static __device__ uint32_t g_Wtf[W_TOTAL];                       // pre-converted tf32 weights
static __device__ float g_X [(size_t)NODES * ND];
static __device__ float g_H0[(size_t)NODES * ND];
static __device__ float g_Hf[(size_t)NODES * ND];
static __device__ float g_P[3][(size_t)KPAD * NDP];              // split-K partials
static __device__ __align__(16) float g_zeroF[4];                // zero-initialized

// ---------------- PTX helpers ----------------
__device__ __forceinline__ void cp16(void* s, const void* g) {
    uint32_t sa = (uint32_t)__cvta_generic_to_shared(s);
    asm volatile("cp.async.cg.shared.global [%0], [%1], 16;\n" :: "r"(sa), "l"(g));
}
__device__ __forceinline__ void cp8(void* s, const void* g) {
    uint32_t sa = (uint32_t)__cvta_generic_to_shared(s);
    asm volatile("cp.async.ca.shared.global [%0], [%1], 8;\n" :: "r"(sa), "l"(g));
}
__device__ __forceinline__ void cp_commit() { asm volatile("cp.async.commit_group;\n" ::); }
__device__ __forceinline__ void cp_wait1()  { asm volatile("cp.async.wait_group 1;\n" ::: "memory"); }

__device__ __forceinline__ void ldsm_x4(uint32_t* r, const void* p) {
    uint32_t sa = (uint32_t)__cvta_generic_to_shared(p);
    asm volatile("ldmatrix.sync.aligned.m8n8.x4.shared.b16 {%0,%1,%2,%3}, [%4];\n"
                 : "=r"(r[0]), "=r"(r[1]), "=r"(r[2]), "=r"(r[3]) : "r"(sa));
}
__device__ __forceinline__ void ldsm_x4_t(uint32_t* r, const void* p) {
    uint32_t sa = (uint32_t)__cvta_generic_to_shared(p);
    asm volatile("ldmatrix.sync.aligned.m8n8.x4.trans.shared.b16 {%0,%1,%2,%3}, [%4];\n"
                 : "=r"(r[0]), "=r"(r[1]), "=r"(r[2]), "=r"(r[3]) : "r"(sa));
}
__device__ __forceinline__ void ldsm_x2_t(uint32_t* r, const void* p) {
    uint32_t sa = (uint32_t)__cvta_generic_to_shared(p);
    asm volatile("ldmatrix.sync.aligned.m8n8.x2.trans.shared.b16 {%0,%1}, [%2];\n"
                 : "=r"(r[0]), "=r"(r[1]) : "r"(sa));
}
__device__ __forceinline__ void mma_bf16(float* c, const uint32_t* a, const uint32_t* b) {
    asm volatile("mma.sync.aligned.m16n8k16.row.col.f32.bf16.bf16.f32 "
                 "{%0,%1,%2,%3},{%4,%5,%6,%7},{%8,%9},{%0,%1,%2,%3};\n"
                 : "+f"(c[0]), "+f"(c[1]), "+f"(c[2]), "+f"(c[3])
                 : "r"(a[0]), "r"(a[1]), "r"(a[2]), "r"(a[3]), "r"(b[0]), "r"(b[1]));
}
__device__ __forceinline__ void mma_tf32(float* c, uint32_t a0, uint32_t a1, uint32_t a2,
                                         uint32_t a3, uint32_t b0, uint32_t b1) {
    asm volatile("mma.sync.aligned.m16n8k8.row.col.f32.tf32.tf32.f32 "
                 "{%0,%1,%2,%3},{%4,%5,%6,%7},{%8,%9},{%0,%1,%2,%3};\n"
                 : "+f"(c[0]), "+f"(c[1]), "+f"(c[2]), "+f"(c[3])
                 : "r"(a0), "r"(a1), "r"(a2), "r"(a3), "r"(b0), "r"(b1));
}
__device__ __forceinline__ uint32_t f2tf32(float x) {
    uint32_t r; asm("cvt.rna.tf32.f32 %0, %1;" : "=r"(r) : "f"(x)); return r;
}

// ---------------- adj fp32 -> bf16 padded [KPAD x KPAD] ----------------
__global__ void k_conv_adj(const float* __restrict__ adj) {
    size_t idx = (size_t)blockIdx.x * blockDim.x + threadIdx.x;
    if (idx >= (size_t)KPAD * (KPAD / 8)) return;
    int r  = (int)(idx / (KPAD / 8));
    int c0 = (int)(idx % (KPAD / 8)) * 8;
    __align__(16) __nv_bfloat162 o[4];
    if (r < NODES && c0 + 8 <= NODES) {
        const float4 v0 = *reinterpret_cast<const float4*>(adj + (size_t)r * NODES + c0);
        const float4 v1 = *reinterpret_cast<const float4*>(adj + (size_t)r * NODES + c0 + 4);
        o[0] = __floats2bfloat162_rn(v0.x, v0.y);
        o[1] = __floats2bfloat162_rn(v0.z, v0.w);
        o[2] = __floats2bfloat162_rn(v1.x, v1.y);
        o[3] = __floats2bfloat162_rn(v1.z, v1.w);
    } else {
        #pragma unroll
        for (int j = 0; j < 4; j++) {
            int c = c0 + j * 2;
            float x0 = (r < NODES && c     < NODES) ? adj[(size_t)r * NODES + c]     : 0.f;
            float x1 = (r < NODES && c + 1 < NODES) ? adj[(size_t)r * NODES + c + 1] : 0.f;
            o[j] = __floats2bfloat162_rn(x0, x1);
        }
    }
    *reinterpret_cast<uint4*>(g_adjBF + (size_t)r * KPAD + c0) =
        *reinterpret_cast<const uint4*>(o);
}

__global__ void k_zero_hbf() {
    size_t i = (size_t)blockIdx.x * blockDim.x + threadIdx.x;
    if (i < (size_t)KPAD * NDP * sizeof(__nv_bfloat16) / 16)
        reinterpret_cast<uint4*>(g_Hbf)[i] = make_uint4(0, 0, 0, 0);
}

// pre-convert all weight matrices to tf32 bit patterns (round-to-nearest)
__global__ void k_convW(const float* __restrict__ Wa, const float* __restrict__ Wv,
                        const float* __restrict__ Wl, const float* __restrict__ W0,
                        const float* __restrict__ convW) {
    int i = blockIdx.x * blockDim.x + threadIdx.x;
    if (i >= W_TOTAL) return;
    float v;
    if      (i < WV_OFF) v = Wa[i - WA_OFF];
    else if (i < WL_OFF) v = Wv[i - WV_OFF];
    else if (i < W0_OFF) v = Wl[i - WL_OFF];
    else if (i < WC_OFF) v = W0[i - W0_OFF];
    else                 v = convW[i - WC_OFF];
    g_Wtf[i] = f2tf32(v);
}

// ---------------- adj GEMM (bf16): split-K partials P[ksp] = adjBF[:,ks] @ Hbf[ks,:] ----
// BM=128, BN=208, BK=64, 3 stages, grid (47,3). 256 threads. (proven in R6)
#define AJ_BM 128
#define AJ_BK 64
#define AJ_A_EL (AJ_BM * 72)      // [128][64+8] bf16
#define AJ_B_EL (AJ_BK * 216)     // [64][208+8] bf16
#define AJ_STG_EL (AJ_A_EL + AJ_B_EL)
#define AJ_SMEM_BYTES (3 * AJ_STG_EL * 2)    // 138240

__global__ __launch_bounds__(256, 1) void k_adj_bf16() {
    extern __shared__ __nv_bfloat16 aj_sm[];

    const int tid  = threadIdx.x;
    const int lane = tid & 31;
    const int warp = tid >> 5;
    const int wm   = warp >> 1;
    const int wn   = warp & 1;
    const int bm0  = blockIdx.x * AJ_BM;
    const int ksp  = blockIdx.y;
    const int kbase = ksp * 2048;
    const int ITERS = (ksp == 2) ? 30 : 32;

    float acc[2][13][4];
    #pragma unroll
    for (int a = 0; a < 2; a++)
        #pragma unroll
        for (int i = 0; i < 13; i++)
            #pragma unroll
            for (int j = 0; j < 4; j++) acc[a][i][j] = 0.f;

    auto fill = [&](int st, int it) {
        const int k0 = kbase + it * AJ_BK;
        __nv_bfloat16* sA = aj_sm + st * AJ_STG_EL;
        __nv_bfloat16* sB = sA + AJ_A_EL;
        #pragma unroll
        for (int v = tid; v < 1024; v += 256) {        // A: 128 x 64
            int r = v >> 3, c = (v & 7) * 8;
            cp16(sA + r * 72 + c, g_adjBF + (size_t)(bm0 + r) * KPAD + k0 + c);
        }
        #pragma unroll
        for (int v = tid; v < 1664; v += 256) {        // B: 64 x 208
            int r = v / 26, nc = (v % 26) * 8;
            cp16(sB + r * 216 + nc, g_Hbf + (size_t)(k0 + r) * NDP + nc);
        }
        cp_commit();
    };

    fill(0, 0);
    fill(1, 1);

    #pragma unroll 1
    for (int it = 0; it < ITERS; ++it) {
        cp_wait1();
        __syncthreads();
        const int st = it % 3;
        const __nv_bfloat16* sA = aj_sm + st * AJ_STG_EL;
        const __nv_bfloat16* sB = sA + AJ_A_EL;
        #pragma unroll
        for (int ks = 0; ks < 4; ks++) {
            uint32_t af[2][4];
            #pragma unroll
            for (int mf = 0; mf < 2; mf++)
                ldsm_x4(af[mf], sA + (wm * 32 + mf * 16 + (lane & 15)) * 72
                                   + ks * 16 + ((lane >> 4) << 3));
            uint32_t bf[13][2];
            #pragma unroll
            for (int ng = 0; ng < 6; ng++) {
                uint32_t r[4];
                ldsm_x4_t(r, sB + (ks * 16 + (lane & 15)) * 216
                                + wn * 104 + ng * 16 + ((lane >> 4) << 3));
                bf[ng * 2][0] = r[0];     bf[ng * 2][1] = r[1];
                bf[ng * 2 + 1][0] = r[2]; bf[ng * 2 + 1][1] = r[3];
            }
            {
                uint32_t r[2];
                ldsm_x2_t(r, sB + (ks * 16 + (lane & 15)) * 216 + wn * 104 + 96);
                bf[12][0] = r[0]; bf[12][1] = r[1];
            }
            #pragma unroll
            for (int mf = 0; mf < 2; mf++)
                #pragma unroll
                for (int nf = 0; nf < 13; nf++)
                    mma_bf16(acc[mf][nf], af[mf], bf[nf]);
        }
        if (it + 2 < ITERS) fill((it + 2) % 3, it + 2);
        else                cp_commit();
    }

    // partial epilogue -> g_P[ksp]
    float* P = g_P[ksp];
    #pragma unroll
    for (int mf = 0; mf < 2; mf++) {
        const int r0 = bm0 + wm * 32 + mf * 16 + (lane >> 2);
        #pragma unroll
        for (int nf = 0; nf < 13; nf++) {
            int c = wn * 104 + nf * 8 + ((lane & 3) << 1);
            *reinterpret_cast<float2*>(&P[(size_t)r0 * NDP + c]) =
                make_float2(acc[mf][nf][0], acc[mf][nf][1]);
            *reinterpret_cast<float2*>(&P[(size_t)(r0 + 8) * NDP + c]) =
                make_float2(acc[mf][nf][2], acc[mf][nf][3]);
        }
    }
}

// ---------------- tf32 GEMM body: C = A[M,K] @ W[K,200], fused epilogues ----------------
// BM=64, BN=208, BK=32, 3 stages. 256 threads. B pre-converted to tf32 bits (no mainloop cvt).
// A smem stride 36 words -> conflict-free LDS (bank = 4m+k covers all 32).
// mode 0: X[row_off+m] = acc + bias
// mode 1: X[row_off+m] = acc + bias + spk_emb[argmax(qmask)]
// mode 2: h0 = relu(acc+bias) -> H0, Hbf
// mode 3: A = [hi | h0] assembled in fill (hi = P0+P1+P2), K=400;
//         h = relu(theta*acc + (1-theta)*(0.9*hi + 0.1*h0)) -> Hf, Hbf
#define G2_BM 64
#define G2_BK 32
#define G2_LDA 36
#define G2_A_EL (G2_BM * G2_LDA)          // 2304
#define G2_B_EL (G2_BK * 216)             // 6912
#define G2_STG_EL (G2_A_EL + G2_B_EL)     // 9216
#define G2_SMEM_BYTES (3 * G2_STG_EL * 4) // 110592

__device__ __forceinline__ void g2_body(
    float* dyn, const float* __restrict__ A, int lda, int M, int K,
    const uint32_t* __restrict__ W, const float* __restrict__ bias,
    int mode, float theta, int row_off,
    const float* __restrict__ qmask, const float* __restrict__ spk_emb)
{
    const int tid  = threadIdx.x;
    const int lane = tid & 31;
    const int warp = tid >> 5;
    const int wm   = warp >> 1;
    const int wn   = warp & 1;
    const int bm0  = blockIdx.x * G2_BM;

    float acc[13][4];
    #pragma unroll
    for (int i = 0; i < 13; i++)
        #pragma unroll
        for (int j = 0; j < 4; j++) acc[i][j] = 0.f;

    auto fill = [&](int st, int it) {
        const int k0 = it * G2_BK;
        float* shA = dyn + st * G2_STG_EL;
        uint32_t* shB = reinterpret_cast<uint32_t*>(shA + G2_A_EL);
        if (mode == 3) {
            #pragma unroll
            for (int v = tid; v < 1024; v += 256) {   // 64 rows x 16 float2
                int m = v >> 4, kp = (v & 15) * 2;
                int gm = bm0 + m, gk = k0 + kp;
                float2 val = make_float2(0.f, 0.f);
                if (gm < M && gk < K) {
                    if (gk < ND) {
                        size_t o = (size_t)gm * NDP + gk;
                        float2 p0 = *reinterpret_cast<const float2*>(&g_P[0][o]);
                        float2 p1 = *reinterpret_cast<const float2*>(&g_P[1][o]);
                        float2 p2 = *reinterpret_cast<const float2*>(&g_P[2][o]);
                        val = make_float2(p0.x + p1.x + p2.x, p0.y + p1.y + p2.y);
                    } else {
                        val = *reinterpret_cast<const float2*>(
                            &g_H0[(size_t)gm * ND + (gk - ND)]);
                    }
                }
                *reinterpret_cast<float2*>(shA + m * G2_LDA + kp) = val;
            }
        } else {
            #pragma unroll
            for (int v = tid; v < 1024; v += 256) {
                int m = v >> 4, kp = (v & 15) * 2;
                int gm = bm0 + m, gk = k0 + kp;
                const float* src = (gm < M && gk < K) ? &A[(size_t)gm * lda + gk] : g_zeroF;
                cp8(shA + m * G2_LDA + kp, src);
            }
        }
        for (int v = tid; v < 3328; v += 256) {      // B: 32 x 208 (tf32 bits)
            int k = v / 104, np = (v % 104) * 2;
            int gk = k0 + k;
            const void* src = (gk < K && np < ND)
                ? (const void*)&W[(size_t)gk * ND + np] : (const void*)g_zeroF;
            cp8(shB + k * 216 + np, src);
        }
        cp_commit();
    };

    const int ITERS = (K + G2_BK - 1) / G2_BK;
    fill(0, 0);
    if (ITERS > 1) fill(1, 1); else cp_commit();

    const int mrow = wm * 16 + (lane >> 2);
    #pragma unroll 1
    for (int it = 0; it < ITERS; ++it) {
        cp_wait1();
        __syncthreads();
        const int st = it % 3;
        const float* shA = dyn + st * G2_STG_EL;
        const uint32_t* shB = reinterpret_cast<const uint32_t*>(shA + G2_A_EL);
        #pragma unroll
        for (int kb = 0; kb < G2_BK; kb += 8) {
            const int kk = kb + (lane & 3);
            uint32_t a0 = f2tf32(shA[mrow * G2_LDA + kk]);
            uint32_t a1 = f2tf32(shA[(mrow + 8) * G2_LDA + kk]);
            uint32_t a2 = f2tf32(shA[mrow * G2_LDA + kk + 4]);
            uint32_t a3 = f2tf32(shA[(mrow + 8) * G2_LDA + kk + 4]);
            #pragma unroll
            for (int nf = 0; nf < 13; nf++) {
                int nc = wn * 104 + nf * 8 + (lane >> 2);
                uint32_t b0 = shB[(kb + (lane & 3)) * 216 + nc];
                uint32_t b1 = shB[(kb + 4 + (lane & 3)) * 216 + nc];
                mma_tf32(acc[nf], a0, a1, a2, a3, b0, b1);
            }
        }
        if (it + 2 < ITERS) fill((it + 2) % 3, it + 2);
        else                cp_commit();
    }

    // fused epilogue (c always even; pair in range iff c < ND)
    const int mloc = wm * 16 + (lane >> 2);
    #pragma unroll
    for (int nf = 0; nf < 13; nf++) {
        int c = wn * 104 + nf * 8 + ((lane & 3) << 1);
        if (c >= ND) continue;
        #pragma unroll
        for (int half = 0; half < 2; half++) {
            int m = bm0 + mloc + half * 8;
            if (m >= M) continue;
            float v0 = acc[nf][half * 2], v1 = acc[nf][half * 2 + 1];
            if (mode <= 1) {
                float x0 = v0 + bias[c], x1 = v1 + bias[c + 1];
                if (mode == 1) {
                    int b = m / 100, t = m % 100;
                    float q0 = qmask[(t * 20 + b) * 2];
                    float q1 = qmask[(t * 20 + b) * 2 + 1];
                    int idx = (q1 > q0) ? 1 : 0;
                    x0 += spk_emb[idx * ND + c];
                    x1 += spk_emb[idx * ND + c + 1];
                }
                *reinterpret_cast<float2*>(&g_X[(size_t)(row_off + m) * ND + c]) =
                    make_float2(x0, x1);
            } else if (mode == 2) {
                float x0 = fmaxf(v0 + bias[c], 0.f);
                float x1 = fmaxf(v1 + bias[c + 1], 0.f);
                *reinterpret_cast<float2*>(&g_H0[(size_t)m * ND + c]) = make_float2(x0, x1);
                *reinterpret_cast<__nv_bfloat162*>(&g_Hbf[(size_t)m * NDP + c]) =
                    __floats2bfloat162_rn(x0, x1);
            } else {
                size_t o = (size_t)m * NDP + c;
                float2 p0 = *reinterpret_cast<const float2*>(&g_P[0][o]);
                float2 p1 = *reinterpret_cast<const float2*>(&g_P[1][o]);
                float2 p2 = *reinterpret_cast<const float2*>(&g_P[2][o]);
                float hix = p0.x + p1.x + p2.x;
                float hiy = p0.y + p1.y + p2.y;
                float2 h0v = *reinterpret_cast<const float2*>(&g_H0[(size_t)m * ND + c]);
                float x0 = fmaxf(theta * v0 + (1.f - theta) * (0.9f * hix + 0.1f * h0v.x), 0.f);
                float x1 = fmaxf(theta * v1 + (1.f - theta) * (0.9f * hiy + 0.1f * h0v.y), 0.f);
                *reinterpret_cast<float2*>(&g_Hf[(size_t)m * ND + c]) = make_float2(x0, x1);
                *reinterpret_cast<__nv_bfloat162*>(&g_Hbf[(size_t)m * NDP + c]) =
                    __floats2bfloat162_rn(x0, x1);
            }
        }
    }
}

// merged modality projections: grid (32, 3)
__global__ __launch_bounds__(256, 1) void k_proj(
    const float* __restrict__ a, const float* __restrict__ v, const float* __restrict__ l,
    const float* __restrict__ ba, const float* __restrict__ bv,
    const float* __restrict__ bl,
    const float* __restrict__ qm, const float* __restrict__ spk)
{
    extern __shared__ float dyn[];
    if (blockIdx.y == 0)
        g2_body(dyn, a, 300,  N_UTT, 300,  g_Wtf + WA_OFF, ba, 0, 0.f, 0,    nullptr, nullptr);
    else if (blockIdx.y == 1)
        g2_body(dyn, v, 342,  N_UTT, 342,  g_Wtf + WV_OFF, bv, 0, 0.f, 2000, nullptr, nullptr);
    else
        g2_body(dyn, l, 1024, N_UTT, 1024, g_Wtf + WL_OFF, bl, 1, 0.f, 4000, qm, spk);
}

// generic tf32 GEMM. asel 1 -> A = g_X (mode 2); mode 3 assembles A in fill. woff -> g_Wtf.
__global__ __launch_bounds__(256, 1) void k_gemm_tf32(
    int asel, int lda, int M, int K,
    int woff, const float* __restrict__ bias,
    int mode, float theta)
{
    extern __shared__ float dyn[];
    const float* A = (asel == 1) ? g_X : g_H0;
    g2_body(dyn, A, lda, M, K, g_Wtf + woff, bias, mode, theta, 0, nullptr, nullptr);
}

// ---------------- output assembly: [2000, 1200] ----------------
__global__ void k_out(float* __restrict__ out) {
    int i = blockIdx.x * blockDim.x + threadIdx.x;
    if (i >= N_UTT * 1200) return;
    int r = i / 1200, c = i % 1200;
    int seg = c / ND, cc = c % ND;
    int chunk = seg >> 1;
    const float* src = (seg & 1) ? g_Hf : g_X;
    out[i] = src[(size_t)(chunk * N_UTT + r) * ND + cc];
}

// ---------------- launch ----------------
extern "C" void kernel_launch(void* const* d_in, const int* in_sizes, int n_in,
                              void* d_out, int out_size) {
    const float* a    = (const float*)d_in[0];
    const float* v    = (const float*)d_in[1];
    const float* l    = (const float*)d_in[2];
    const float* qm   = (const float*)d_in[3];
    const float* adj  = (const float*)d_in[4];
    const float* Wa   = (const float*)d_in[5];
    const float* ba   = (const float*)d_in[6];
    const float* Wv   = (const float*)d_in[7];
    const float* bv   = (const float*)d_in[8];
    const float* Wl   = (const float*)d_in[9];
    const float* bl   = (const float*)d_in[10];
    const float* spk  = (const float*)d_in[11];
    const float* W0   = (const float*)d_in[12];
    const float* b0   = (const float*)d_in[13];
    const float* convW= (const float*)d_in[14];
    float* out = (float*)d_out;

    cudaFuncSetAttribute(k_adj_bf16, cudaFuncAttributeMaxDynamicSharedMemorySize, AJ_SMEM_BYTES);
    cudaFuncSetAttribute(k_proj, cudaFuncAttributeMaxDynamicSharedMemorySize, G2_SMEM_BYTES);
    cudaFuncSetAttribute(k_gemm_tf32, cudaFuncAttributeMaxDynamicSharedMemorySize, G2_SMEM_BYTES);

    // 1. adj -> bf16 padded; zero bf16 h buffer; pre-convert weights
    {
        size_t total = (size_t)KPAD * (KPAD / 8);
        k_conv_adj<<<(unsigned)((total + 255) / 256), 256>>>(adj);
    }
    {
        size_t chunks = (size_t)KPAD * NDP * sizeof(__nv_bfloat16) / 16;
        k_zero_hbf<<<(unsigned)((chunks + 255) / 256), 256>>>();
    }
    k_convW<<<(W_TOTAL + 255) / 256, 256>>>(Wa, Wv, Wl, W0, convW);

    // 2. modality projections (one launch)
    {
        dim3 g((N_UTT + G2_BM - 1) / G2_BM, 3);
        k_proj<<<g, 256, G2_SMEM_BYTES>>>(a, v, l, ba, bv, bl, qm, spk);
    }

    // 3. h0 = relu(X @ W0 + b0) -> H0, Hbf
    k_gemm_tf32<<<(NODES + G2_BM - 1) / G2_BM, 256, G2_SMEM_BYTES>>>(
        1, ND, NODES, ND, W0_OFF, b0, 2, 0.f);

    // 4. GCNII layers (adj split-K partials; reduce fused into mode-3 fill)
    for (int k = 0; k < NLAYERS; ++k) {
        float theta = logf(0.5f / (float)(k + 1) + 1.0f);
        dim3 ga(KPAD / AJ_BM, 3);
        k_adj_bf16<<<ga, 256, AJ_SMEM_BYTES>>>();
        k_gemm_tf32<<<(NODES + G2_BM - 1) / G2_BM, 256, G2_SMEM_BYTES>>>(
            2, ND2, NODES, ND2, WC_OFF + k * ND2 * ND, nullptr, 3, theta);
    }

    // 5. gather output
    k_out<<<(N_UTT * 1200 + 255) / 256, 256>>>(out);
}

// round 12
// speedup vs baseline: 1.1555x; 1.1115x over previous
#include <cuda_runtime.h>
#include <cuda_bf16.h>
#include <cstdint>
#include <math.h>

// ---------------- problem constants ----------------
#define N_UTT   2000
#define NODES   6000
#define KPAD    6016     // 47*128, 94*64
#define ND      200
#define NDP     208
#define ND2     400
#define NLAYERS 8

// W offsets inside g_Wtf (tf32-bit u32)
#define WA_OFF 0
#define WV_OFF 60000
#define WL_OFF 128400
#define W0_OFF 333200
#define WC_OFF 373200
#define W_TOTAL 1013200

// ---------------- device scratch ----------------
static __device__ __nv_bfloat16 g_adjBF[(size_t)KPAD * KPAD];    // 72.4 MB
static __device__ __nv_bfloat16 g_Hbf[(size_t)KPAD * NDP];       // h bf16 [node][feat], pads 0
static __device__ uint32_t g_Wtf[W_TOTAL];                       // pre-converted tf32 weights
static __device__ float g_X [(size_t)NODES * ND];
static __device__ float g_H0[(size_t)NODES * ND];
static __device__ float g_Hf[(size_t)NODES * ND];
static __device__ float g_SUP[(size_t)NODES * ND2];              // [hi | h0]
static __device__ float g_P[3][(size_t)KPAD * NDP];              // split-K partials
static __device__ __align__(16) float g_zeroF[4];                // zero-initialized

// ---------------- PTX helpers ----------------
__device__ __forceinline__ void cp16(void* s, const void* g) {
    uint32_t sa = (uint32_t)__cvta_generic_to_shared(s);
    asm volatile("cp.async.cg.shared.global [%0], [%1], 16;\n" :: "r"(sa), "l"(g));
}
__device__ __forceinline__ void cp8(void* s, const void* g) {
    uint32_t sa = (uint32_t)__cvta_generic_to_shared(s);
    asm volatile("cp.async.ca.shared.global [%0], [%1], 8;\n" :: "r"(sa), "l"(g));
}
__device__ __forceinline__ void cp_commit() { asm volatile("cp.async.commit_group;\n" ::); }
__device__ __forceinline__ void cp_wait1()  { asm volatile("cp.async.wait_group 1;\n" ::: "memory"); }

__device__ __forceinline__ void ldsm_x4(uint32_t* r, const void* p) {
    uint32_t sa = (uint32_t)__cvta_generic_to_shared(p);
    asm volatile("ldmatrix.sync.aligned.m8n8.x4.shared.b16 {%0,%1,%2,%3}, [%4];\n"
                 : "=r"(r[0]), "=r"(r[1]), "=r"(r[2]), "=r"(r[3]) : "r"(sa));
}
__device__ __forceinline__ void ldsm_x4_t(uint32_t* r, const void* p) {
    uint32_t sa = (uint32_t)__cvta_generic_to_shared(p);
    asm volatile("ldmatrix.sync.aligned.m8n8.x4.trans.shared.b16 {%0,%1,%2,%3}, [%4];\n"
                 : "=r"(r[0]), "=r"(r[1]), "=r"(r[2]), "=r"(r[3]) : "r"(sa));
}
__device__ __forceinline__ void ldsm_x2_t(uint32_t* r, const void* p) {
    uint32_t sa = (uint32_t)__cvta_generic_to_shared(p);
    asm volatile("ldmatrix.sync.aligned.m8n8.x2.trans.shared.b16 {%0,%1}, [%2];\n"
                 : "=r"(r[0]), "=r"(r[1]) : "r"(sa));
}
__device__ __forceinline__ void mma_bf16(float* c, const uint32_t* a, const uint32_t* b) {
    asm volatile("mma.sync.aligned.m16n8k16.row.col.f32.bf16.bf16.f32 "
                 "{%0,%1,%2,%3},{%4,%5,%6,%7},{%8,%9},{%0,%1,%2,%3};\n"
                 : "+f"(c[0]), "+f"(c[1]), "+f"(c[2]), "+f"(c[3])
                 : "r"(a[0]), "r"(a[1]), "r"(a[2]), "r"(a[3]), "r"(b[0]), "r"(b[1]));
}
__device__ __forceinline__ void mma_tf32(float* c, uint32_t a0, uint32_t a1, uint32_t a2,
                                         uint32_t a3, uint32_t b0, uint32_t b1) {
    asm volatile("mma.sync.aligned.m16n8k8.row.col.f32.tf32.tf32.f32 "
                 "{%0,%1,%2,%3},{%4,%5,%6,%7},{%8,%9},{%0,%1,%2,%3};\n"
                 : "+f"(c[0]), "+f"(c[1]), "+f"(c[2]), "+f"(c[3])
                 : "r"(a0), "r"(a1), "r"(a2), "r"(a3), "r"(b0), "r"(b1));
}
__device__ __forceinline__ uint32_t f2tf32(float x) {
    uint32_t r; asm("cvt.rna.tf32.f32 %0, %1;" : "=r"(r) : "f"(x)); return r;
}

// ---------------- adj fp32 -> bf16 padded [KPAD x KPAD] ----------------
__global__ void k_conv_adj(const float* __restrict__ adj) {
    size_t idx = (size_t)blockIdx.x * blockDim.x + threadIdx.x;
    if (idx >= (size_t)KPAD * (KPAD / 8)) return;
    int r  = (int)(idx / (KPAD / 8));
    int c0 = (int)(idx % (KPAD / 8)) * 8;
    __align__(16) __nv_bfloat162 o[4];
    if (r < NODES && c0 + 8 <= NODES) {
        const float4 v0 = *reinterpret_cast<const float4*>(adj + (size_t)r * NODES + c0);
        const float4 v1 = *reinterpret_cast<const float4*>(adj + (size_t)r * NODES + c0 + 4);
        o[0] = __floats2bfloat162_rn(v0.x, v0.y);
        o[1] = __floats2bfloat162_rn(v0.z, v0.w);
        o[2] = __floats2bfloat162_rn(v1.x, v1.y);
        o[3] = __floats2bfloat162_rn(v1.z, v1.w);
    } else {
        #pragma unroll
        for (int j = 0; j < 4; j++) {
            int c = c0 + j * 2;
            float x0 = (r < NODES && c     < NODES) ? adj[(size_t)r * NODES + c]     : 0.f;
            float x1 = (r < NODES && c + 1 < NODES) ? adj[(size_t)r * NODES + c + 1] : 0.f;
            o[j] = __floats2bfloat162_rn(x0, x1);
        }
    }
    *reinterpret_cast<uint4*>(g_adjBF + (size_t)r * KPAD + c0) =
        *reinterpret_cast<const uint4*>(o);
}

__global__ void k_zero_hbf() {
    size_t i = (size_t)blockIdx.x * blockDim.x + threadIdx.x;
    if (i < (size_t)KPAD * NDP * sizeof(__nv_bfloat16) / 16)
        reinterpret_cast<uint4*>(g_Hbf)[i] = make_uint4(0, 0, 0, 0);
}

// pre-convert all weight matrices to tf32 bit patterns (round-to-nearest)
__global__ void k_convW(const float* __restrict__ Wa, const float* __restrict__ Wv,
                        const float* __restrict__ Wl, const float* __restrict__ W0,
                        const float* __restrict__ convW) {
    int i = blockIdx.x * blockDim.x + threadIdx.x;
    if (i >= W_TOTAL) return;
    float v;
    if      (i < WV_OFF) v = Wa[i - WA_OFF];
    else if (i < WL_OFF) v = Wv[i - WV_OFF];
    else if (i < W0_OFF) v = Wl[i - WL_OFF];
    else if (i < WC_OFF) v = W0[i - W0_OFF];
    else                 v = convW[i - WC_OFF];
    g_Wtf[i] = f2tf32(v);
}

// ---------------- adj GEMM (bf16): split-K partials P[ksp] = adjBF[:,ks] @ Hbf[ks,:] ----
// BM=128, BN=208, BK=64, 3 stages, grid (47,3). 256 threads. (proven in R6)
#define AJ_BM 128
#define AJ_BK 64
#define AJ_A_EL (AJ_BM * 72)      // [128][64+8] bf16
#define AJ_B_EL (AJ_BK * 216)     // [64][208+8] bf16
#define AJ_STG_EL (AJ_A_EL + AJ_B_EL)
#define AJ_SMEM_BYTES (3 * AJ_STG_EL * 2)    // 138240

__global__ __launch_bounds__(256, 1) void k_adj_bf16() {
    extern __shared__ __nv_bfloat16 aj_sm[];

    const int tid  = threadIdx.x;
    const int lane = tid & 31;
    const int warp = tid >> 5;
    const int wm   = warp >> 1;
    const int wn   = warp & 1;
    const int bm0  = blockIdx.x * AJ_BM;
    const int ksp  = blockIdx.y;
    const int kbase = ksp * 2048;
    const int ITERS = (ksp == 2) ? 30 : 32;

    float acc[2][13][4];
    #pragma unroll
    for (int a = 0; a < 2; a++)
        #pragma unroll
        for (int i = 0; i < 13; i++)
            #pragma unroll
            for (int j = 0; j < 4; j++) acc[a][i][j] = 0.f;

    auto fill = [&](int st, int it) {
        const int k0 = kbase + it * AJ_BK;
        __nv_bfloat16* sA = aj_sm + st * AJ_STG_EL;
        __nv_bfloat16* sB = sA + AJ_A_EL;
        #pragma unroll
        for (int v = tid; v < 1024; v += 256) {        // A: 128 x 64
            int r = v >> 3, c = (v & 7) * 8;
            cp16(sA + r * 72 + c, g_adjBF + (size_t)(bm0 + r) * KPAD + k0 + c);
        }
        #pragma unroll
        for (int v = tid; v < 1664; v += 256) {        // B: 64 x 208
            int r = v / 26, nc = (v % 26) * 8;
            cp16(sB + r * 216 + nc, g_Hbf + (size_t)(k0 + r) * NDP + nc);
        }
        cp_commit();
    };

    fill(0, 0);
    fill(1, 1);

    #pragma unroll 1
    for (int it = 0; it < ITERS; ++it) {
        cp_wait1();
        __syncthreads();
        const int st = it % 3;
        const __nv_bfloat16* sA = aj_sm + st * AJ_STG_EL;
        const __nv_bfloat16* sB = sA + AJ_A_EL;
        #pragma unroll
        for (int ks = 0; ks < 4; ks++) {
            uint32_t af[2][4];
            #pragma unroll
            for (int mf = 0; mf < 2; mf++)
                ldsm_x4(af[mf], sA + (wm * 32 + mf * 16 + (lane & 15)) * 72
                                   + ks * 16 + ((lane >> 4) << 3));
            uint32_t bf[13][2];
            #pragma unroll
            for (int ng = 0; ng < 6; ng++) {
                uint32_t r[4];
                ldsm_x4_t(r, sB + (ks * 16 + (lane & 15)) * 216
                                + wn * 104 + ng * 16 + ((lane >> 4) << 3));
                bf[ng * 2][0] = r[0];     bf[ng * 2][1] = r[1];
                bf[ng * 2 + 1][0] = r[2]; bf[ng * 2 + 1][1] = r[3];
            }
            {
                uint32_t r[2];
                ldsm_x2_t(r, sB + (ks * 16 + (lane & 15)) * 216 + wn * 104 + 96);
                bf[12][0] = r[0]; bf[12][1] = r[1];
            }
            #pragma unroll
            for (int mf = 0; mf < 2; mf++)
                #pragma unroll
                for (int nf = 0; nf < 13; nf++)
                    mma_bf16(acc[mf][nf], af[mf], bf[nf]);
        }
        if (it + 2 < ITERS) fill((it + 2) % 3, it + 2);
        else                cp_commit();
    }

    // partial epilogue -> g_P[ksp]
    float* P = g_P[ksp];
    #pragma unroll
    for (int mf = 0; mf < 2; mf++) {
        const int r0 = bm0 + wm * 32 + mf * 16 + (lane >> 2);
        #pragma unroll
        for (int nf = 0; nf < 13; nf++) {
            int c = wn * 104 + nf * 8 + ((lane & 3) << 1);
            *reinterpret_cast<float2*>(&P[(size_t)r0 * NDP + c]) =
                make_float2(acc[mf][nf][0], acc[mf][nf][1]);
            *reinterpret_cast<float2*>(&P[(size_t)(r0 + 8) * NDP + c]) =
                make_float2(acc[mf][nf][2], acc[mf][nf][3]);
        }
    }
}

// ---------------- reduce partials -> SUP[:,0:200] ----------------
__global__ void k_reduce() {
    int i = blockIdx.x * blockDim.x + threadIdx.x;
    if (i >= NODES * 50) return;
    int r = i / 50, c = (i % 50) * 4;
    size_t o = (size_t)r * NDP + c;
    float4 p0 = *reinterpret_cast<const float4*>(&g_P[0][o]);
    float4 p1 = *reinterpret_cast<const float4*>(&g_P[1][o]);
    float4 p2 = *reinterpret_cast<const float4*>(&g_P[2][o]);
    float4 s = make_float4(p0.x + p1.x + p2.x, p0.y + p1.y + p2.y,
                           p0.z + p1.z + p2.z, p0.w + p1.w + p2.w);
    *reinterpret_cast<float4*>(&g_SUP[(size_t)r * ND2 + c]) = s;
}

// ---------------- tf32 GEMM body: C = A[M,K] @ W[K,200], fused epilogues ----------------
// BM=64, BN=208, BK=32, 3 stages. 256 threads. B pre-converted to tf32 bits (no mainloop cvt).
// A smem stride 36 words -> conflict-free LDS.
// mode 0: X[row_off+m] = acc + bias
// mode 1: X[row_off+m] = acc + bias + spk_emb[argmax(qmask)]
// mode 2: h0 = relu(acc+bias) -> H0, SUP[:,200:400], Hbf
// mode 3: A = g_SUP (K=400); h = relu(theta*acc + (1-theta)*(0.9*hi + 0.1*h0)) -> Hf, Hbf
#define G2_BM 64
#define G2_BK 32
#define G2_LDA 36
#define G2_A_EL (G2_BM * G2_LDA)          // 2304
#define G2_B_EL (G2_BK * 216)             // 6912
#define G2_STG_EL (G2_A_EL + G2_B_EL)     // 9216
#define G2_SMEM_BYTES (3 * G2_STG_EL * 4) // 110592

__device__ __forceinline__ void g2_body(
    float* dyn, const float* __restrict__ A, int lda, int M, int K,
    const uint32_t* __restrict__ W, const float* __restrict__ bias,
    int mode, float theta, int row_off,
    const float* __restrict__ qmask, const float* __restrict__ spk_emb)
{
    const int tid  = threadIdx.x;
    const int lane = tid & 31;
    const int warp = tid >> 5;
    const int wm   = warp >> 1;
    const int wn   = warp & 1;
    const int bm0  = blockIdx.x * G2_BM;

    float acc[13][4];
    #pragma unroll
    for (int i = 0; i < 13; i++)
        #pragma unroll
        for (int j = 0; j < 4; j++) acc[i][j] = 0.f;

    auto fill = [&](int st, int it) {
        const int k0 = it * G2_BK;
        float* shA = dyn + st * G2_STG_EL;
        uint32_t* shB = reinterpret_cast<uint32_t*>(shA + G2_A_EL);
        #pragma unroll
        for (int v = tid; v < 1024; v += 256) {      // A: 64 x 32 in 8B chunks
            int m = v >> 4, kp = (v & 15) * 2;
            int gm = bm0 + m, gk = k0 + kp;
            const float* src = (gm < M && gk < K) ? &A[(size_t)gm * lda + gk] : g_zeroF;
            cp8(shA + m * G2_LDA + kp, src);
        }
        for (int v = tid; v < 3328; v += 256) {      // B: 32 x 208 (tf32 bits)
            int k = v / 104, np = (v % 104) * 2;
            int gk = k0 + k;
            const void* src = (gk < K && np < ND)
                ? (const void*)&W[(size_t)gk * ND + np] : (const void*)g_zeroF;
            cp8(shB + k * 216 + np, src);
        }
        cp_commit();
    };

    const int ITERS = (K + G2_BK - 1) / G2_BK;
    fill(0, 0);
    if (ITERS > 1) fill(1, 1); else cp_commit();

    const int mrow = wm * 16 + (lane >> 2);
    #pragma unroll 1
    for (int it = 0; it < ITERS; ++it) {
        cp_wait1();
        __syncthreads();
        const int st = it % 3;
        const float* shA = dyn + st * G2_STG_EL;
        const uint32_t* shB = reinterpret_cast<const uint32_t*>(shA + G2_A_EL);
        #pragma unroll
        for (int kb = 0; kb < G2_BK; kb += 8) {
            const int kk = kb + (lane & 3);
            uint32_t a0 = f2tf32(shA[mrow * G2_LDA + kk]);
            uint32_t a1 = f2tf32(shA[(mrow + 8) * G2_LDA + kk]);
            uint32_t a2 = f2tf32(shA[mrow * G2_LDA + kk + 4]);
            uint32_t a3 = f2tf32(shA[(mrow + 8) * G2_LDA + kk + 4]);
            #pragma unroll
            for (int nf = 0; nf < 13; nf++) {
                int nc = wn * 104 + nf * 8 + (lane >> 2);
                uint32_t b0 = shB[(kb + (lane & 3)) * 216 + nc];
                uint32_t b1 = shB[(kb + 4 + (lane & 3)) * 216 + nc];
                mma_tf32(acc[nf], a0, a1, a2, a3, b0, b1);
            }
        }
        if (it + 2 < ITERS) fill((it + 2) % 3, it + 2);
        else                cp_commit();
    }

    // fused epilogue (c always even; pair in range iff c < ND)
    const int mloc = wm * 16 + (lane >> 2);
    #pragma unroll
    for (int nf = 0; nf < 13; nf++) {
        int c = wn * 104 + nf * 8 + ((lane & 3) << 1);
        if (c >= ND) continue;
        #pragma unroll
        for (int half = 0; half < 2; half++) {
            int m = bm0 + mloc + half * 8;
            if (m >= M) continue;
            float v0 = acc[nf][half * 2], v1 = acc[nf][half * 2 + 1];
            if (mode <= 1) {
                float x0 = v0 + bias[c], x1 = v1 + bias[c + 1];
                if (mode == 1) {
                    int b = m / 100, t = m % 100;
                    float q0 = qmask[(t * 20 + b) * 2];
                    float q1 = qmask[(t * 20 + b) * 2 + 1];
                    int idx = (q1 > q0) ? 1 : 0;
                    x0 += spk_emb[idx * ND + c];
                    x1 += spk_emb[idx * ND + c + 1];
                }
                *reinterpret_cast<float2*>(&g_X[(size_t)(row_off + m) * ND + c]) =
                    make_float2(x0, x1);
            } else if (mode == 2) {
                float x0 = fmaxf(v0 + bias[c], 0.f);
                float x1 = fmaxf(v1 + bias[c + 1], 0.f);
                *reinterpret_cast<float2*>(&g_H0[(size_t)m * ND + c]) = make_float2(x0, x1);
                *reinterpret_cast<float2*>(&g_SUP[(size_t)m * ND2 + ND + c]) = make_float2(x0, x1);
                *reinterpret_cast<__nv_bfloat162*>(&g_Hbf[(size_t)m * NDP + c]) =
                    __floats2bfloat162_rn(x0, x1);
            } else {
                float2 hi  = *reinterpret_cast<const float2*>(&g_SUP[(size_t)m * ND2 + c]);
                float2 h0v = *reinterpret_cast<const float2*>(&g_H0[(size_t)m * ND + c]);
                float x0 = fmaxf(theta * v0 + (1.f - theta) * (0.9f * hi.x + 0.1f * h0v.x), 0.f);
                float x1 = fmaxf(theta * v1 + (1.f - theta) * (0.9f * hi.y + 0.1f * h0v.y), 0.f);
                *reinterpret_cast<float2*>(&g_Hf[(size_t)m * ND + c]) = make_float2(x0, x1);
                *reinterpret_cast<__nv_bfloat162*>(&g_Hbf[(size_t)m * NDP + c]) =
                    __floats2bfloat162_rn(x0, x1);
            }
        }
    }
}

// merged modality projections: grid (32, 3)
__global__ __launch_bounds__(256, 1) void k_proj(
    const float* __restrict__ a, const float* __restrict__ v, const float* __restrict__ l,
    const float* __restrict__ ba, const float* __restrict__ bv,
    const float* __restrict__ bl,
    const float* __restrict__ qm, const float* __restrict__ spk)
{
    extern __shared__ float dyn[];
    if (blockIdx.y == 0)
        g2_body(dyn, a, 300,  N_UTT, 300,  g_Wtf + WA_OFF, ba, 0, 0.f, 0,    nullptr, nullptr);
    else if (blockIdx.y == 1)
        g2_body(dyn, v, 342,  N_UTT, 342,  g_Wtf + WV_OFF, bv, 0, 0.f, 2000, nullptr, nullptr);
    else
        g2_body(dyn, l, 1024, N_UTT, 1024, g_Wtf + WL_OFF, bl, 1, 0.f, 4000, qm, spk);
}

// generic tf32 GEMM. asel 1 -> A = g_X (mode 2); asel 2 -> A = g_SUP (mode 3).
__global__ __launch_bounds__(256, 1) void k_gemm_tf32(
    int asel, int lda, int M, int K,
    int woff, const float* __restrict__ bias,
    int mode, float theta)
{
    extern __shared__ float dyn[];
    const float* A = (asel == 1) ? g_X : g_SUP;
    g2_body(dyn, A, lda, M, K, g_Wtf + woff, bias, mode, theta, 0, nullptr, nullptr);
}

// ---------------- output assembly: [2000, 1200] ----------------
__global__ void k_out(float* __restrict__ out) {
    int i = blockIdx.x * blockDim.x + threadIdx.x;
    if (i >= N_UTT * 1200) return;
    int r = i / 1200, c = i % 1200;
    int seg = c / ND, cc = c % ND;
    int chunk = seg >> 1;
    const float* src = (seg & 1) ? g_Hf : g_X;
    out[i] = src[(size_t)(chunk * N_UTT + r) * ND + cc];
}

// ---------------- launch ----------------
extern "C" void kernel_launch(void* const* d_in, const int* in_sizes, int n_in,
                              void* d_out, int out_size) {
    const float* a    = (const float*)d_in[0];
    const float* v    = (const float*)d_in[1];
    const float* l    = (const float*)d_in[2];
    const float* qm   = (const float*)d_in[3];
    const float* adj  = (const float*)d_in[4];
    const float* Wa   = (const float*)d_in[5];
    const float* ba   = (const float*)d_in[6];
    const float* Wv   = (const float*)d_in[7];
    const float* bv   = (const float*)d_in[8];
    const float* Wl   = (const float*)d_in[9];
    const float* bl   = (const float*)d_in[10];
    const float* spk  = (const float*)d_in[11];
    const float* W0   = (const float*)d_in[12];
    const float* b0   = (const float*)d_in[13];
    const float* convW= (const float*)d_in[14];
    float* out = (float*)d_out;

    cudaFuncSetAttribute(k_adj_bf16, cudaFuncAttributeMaxDynamicSharedMemorySize, AJ_SMEM_BYTES);
    cudaFuncSetAttribute(k_proj, cudaFuncAttributeMaxDynamicSharedMemorySize, G2_SMEM_BYTES);
    cudaFuncSetAttribute(k_gemm_tf32, cudaFuncAttributeMaxDynamicSharedMemorySize, G2_SMEM_BYTES);

    // 1. adj -> bf16 padded; zero bf16 h buffer; pre-convert weights
    {
        size_t total = (size_t)KPAD * (KPAD / 8);
        k_conv_adj<<<(unsigned)((total + 255) / 256), 256>>>(adj);
    }
    {
        size_t chunks = (size_t)KPAD * NDP * sizeof(__nv_bfloat16) / 16;
        k_zero_hbf<<<(unsigned)((chunks + 255) / 256), 256>>>();
    }
    k_convW<<<(W_TOTAL + 255) / 256, 256>>>(Wa, Wv, Wl, W0, convW);

    // 2. modality projections (one launch)
    {
        dim3 g((N_UTT + G2_BM - 1) / G2_BM, 3);
        k_proj<<<g, 256, G2_SMEM_BYTES>>>(a, v, l, ba, bv, bl, qm, spk);
    }

    // 3. h0 = relu(X @ W0 + b0) -> H0, SUP[:,200:400], Hbf
    k_gemm_tf32<<<(NODES + G2_BM - 1) / G2_BM, 256, G2_SMEM_BYTES>>>(
        1, ND, NODES, ND, W0_OFF, b0, 2, 0.f);

    // 4. GCNII layers
    for (int k = 0; k < NLAYERS; ++k) {
        float theta = logf(0.5f / (float)(k + 1) + 1.0f);
        dim3 ga(KPAD / AJ_BM, 3);
        k_adj_bf16<<<ga, 256, AJ_SMEM_BYTES>>>();
        k_reduce<<<(NODES * 50 + 255) / 256, 256>>>();
        k_gemm_tf32<<<(NODES + G2_BM - 1) / G2_BM, 256, G2_SMEM_BYTES>>>(
            2, ND2, NODES, ND2, WC_OFF + k * ND2 * ND, nullptr, 3, theta);
    }

    // 5. gather output
    k_out<<<(N_UTT * 1200 + 255) / 256, 256>>>(out);
}